// round 7
// baseline (speedup 1.0000x reference)
#include <cuda_runtime.h>
#include <cuda_bf16.h>
#include <cstdint>
#include <cstddef>

// LSTM: B=64, T=512, D=512, H=512, fp32.
// Phase 0: interleave U gates -> g_U4[k*512+h] = (Uc,Ui,Uf,Uo)[k][h]
// Phase 1: P[t][b][g*512+h] = x @ W_g + b_g   (one 32768x2048x512 SGEMM, f32x2 FFMA)
// Phase 2: 512 sequential step kernels; h chained through d_out, c in g_c.

typedef unsigned long long ull;

#define B_ 64
#define T_ 512
#define D_ 512
#define H_ 512

// ---------------- device scratch (static: no allocation APIs) ----------------
__device__ float      g_P[(size_t)T_ * B_ * 2048];   // 256 MB preactivations
__device__ ulonglong2 g_U4[(size_t)D_ * H_];         // 4 MB gate-interleaved U
__device__ float      g_c[(size_t)B_ * H_];          // 128 KB cell state

// ---------------- f32x2 helpers ----------------
__device__ __forceinline__ void ffma2(ull& d, ull a, ull b) {
    asm("fma.rn.f32x2 %0, %1, %2, %0;" : "+l"(d) : "l"(a), "l"(b));
}
__device__ __forceinline__ ull pack2(float v) {
    ull r; asm("mov.b64 %0, {%1, %1};" : "=l"(r) : "f"(v)); return r;
}
__device__ __forceinline__ float2 up2(ull v) {
    float2 r; asm("mov.b64 {%0, %1}, %2;" : "=f"(r.x), "=f"(r.y) : "l"(v)); return r;
}

// ---------------- phase 0: build interleaved U ----------------
__global__ void build_u4(const float* __restrict__ Uc, const float* __restrict__ Ui,
                         const float* __restrict__ Uf, const float* __restrict__ Uo) {
    int i = blockIdx.x * 256 + threadIdx.x;   // i = k*512 + h, grid covers 262144
    float4 v = make_float4(Uc[i], Ui[i], Uf[i], Uo[i]);
    ((float4*)g_U4)[i] = v;
}

// ---------------- phase 1: SGEMM for preactivations ----------------
// C[m][n] = sum_k A[m][k] * W_g[k][h],  m = b*512 + t, n = gate*512 + h
// BM=BN=128, BK=8, 256 threads, 8x8 microtile, f32x2 accumulators (m-paired).
#define BM 128
#define BN 128
#define BK 8

__global__ void gemm_pre(const float* __restrict__ A,
                         const float* __restrict__ Wc, const float* __restrict__ Wi,
                         const float* __restrict__ Wf, const float* __restrict__ Wo,
                         const float* __restrict__ bc, const float* __restrict__ bi,
                         const float* __restrict__ bf, const float* __restrict__ bo) {
    __shared__ __align__(16) float As[BK][BM];
    __shared__ __align__(16) float Bs[BK][BN];

    const int tid   = threadIdx.x;
    const int ntile = blockIdx.x;              // 0..15
    const int m0    = blockIdx.y * BM;         // 0..255 tiles
    const int gate  = ntile >> 2;
    const int hbase = (ntile & 3) * BN;        // within-gate h offset (0..384)
    const float* W    = (gate == 0) ? Wc : (gate == 1) ? Wi : (gate == 2) ? Wf : Wo;
    const float* bias = (gate == 0) ? bc : (gate == 1) ? bi : (gate == 2) ? bf : bo;

    const int a_row = tid >> 1, a_col = (tid & 1) * 4;
    const int b_row = tid >> 5, b_col = (tid & 31) * 4;
    const int tx = tid & 15, ty = tid >> 4;

    ull acc[4][8];
#pragma unroll
    for (int i = 0; i < 4; i++)
#pragma unroll
        for (int j = 0; j < 8; j++) acc[i][j] = 0ull;

    const float* Abase = A + (size_t)(m0 + a_row) * D_ + a_col;
    const float* Wbase = W + (size_t)b_row * H_ + hbase + b_col;

    for (int k0 = 0; k0 < D_; k0 += BK) {
        float4 av = *(const float4*)(Abase + k0);
        As[a_col + 0][a_row] = av.x;
        As[a_col + 1][a_row] = av.y;
        As[a_col + 2][a_row] = av.z;
        As[a_col + 3][a_row] = av.w;
        *(float4*)&Bs[b_row][b_col] = *(const float4*)(Wbase + (size_t)k0 * H_);
        __syncthreads();

#pragma unroll
        for (int kk = 0; kk < BK; kk++) {
            const ull* a64 = (const ull*)&As[kk][0];
            ull aP[4];
            aP[0] = a64[ty * 2];       // m = ty*4+0, +1
            aP[1] = a64[ty * 2 + 1];   // m = ty*4+2, +3
            aP[2] = a64[ty * 2 + 32];  // m = 64+ty*4+0, +1
            aP[3] = a64[ty * 2 + 33];  // m = 64+ty*4+2, +3
            float4 bv0 = *(const float4*)&Bs[kk][tx * 4];
            float4 bv1 = *(const float4*)&Bs[kk][tx * 4 + 64];
            ull bp[8];
            bp[0] = pack2(bv0.x); bp[1] = pack2(bv0.y);
            bp[2] = pack2(bv0.z); bp[3] = pack2(bv0.w);
            bp[4] = pack2(bv1.x); bp[5] = pack2(bv1.y);
            bp[6] = pack2(bv1.z); bp[7] = pack2(bv1.w);
#pragma unroll
            for (int ip = 0; ip < 4; ip++)
#pragma unroll
                for (int j = 0; j < 8; j++) ffma2(acc[ip][j], aP[ip], bp[j]);
        }
        __syncthreads();
    }

    // epilogue: add bias, scatter to g_P[t][b][gate*512 + h]
    float bias0[4], bias1[4];
#pragma unroll
    for (int j = 0; j < 4; j++) {
        bias0[j] = __ldg(&bias[hbase + tx * 4 + j]);
        bias1[j] = __ldg(&bias[hbase + 64 + tx * 4 + j]);
    }
#pragma unroll
    for (int ip = 0; ip < 4; ip++) {
        const int m_l = (ip < 2) ? (ty * 4 + ip * 2) : (64 + ty * 4 + (ip - 2) * 2);
        float2 c0 = up2(acc[ip][0]), c1 = up2(acc[ip][1]);
        float2 c2 = up2(acc[ip][2]), c3 = up2(acc[ip][3]);
        float2 c4 = up2(acc[ip][4]), c5 = up2(acc[ip][5]);
        float2 c6 = up2(acc[ip][6]), c7 = up2(acc[ip][7]);
#pragma unroll
        for (int lane = 0; lane < 2; lane++) {
            const int row = m0 + m_l + lane;        // row = b*512 + t
            const int b = row >> 9, t = row & 511;
            float* dst = g_P + ((size_t)(t * B_ + b)) * 2048 + (size_t)gate * 512 + hbase;
            float4 v0, v1;
            if (lane == 0) {
                v0 = make_float4(c0.x + bias0[0], c1.x + bias0[1], c2.x + bias0[2], c3.x + bias0[3]);
                v1 = make_float4(c4.x + bias1[0], c5.x + bias1[1], c6.x + bias1[2], c7.x + bias1[3]);
            } else {
                v0 = make_float4(c0.y + bias0[0], c1.y + bias0[1], c2.y + bias0[2], c3.y + bias0[3]);
                v1 = make_float4(c4.y + bias1[0], c5.y + bias1[1], c6.y + bias1[2], c7.y + bias1[3]);
            }
            *(float4*)(dst + tx * 4)      = v0;
            *(float4*)(dst + 64 + tx * 4) = v1;
        }
    }
}

// ---------------- phase 2: one timestep ----------------
// Grid 128 CTAs: blockIdx = bg*32 + hg; tile = 16 b x 16 h.
// 256 threads: h_l = tid&15, bq = (tid>>4)&3 (4 b's each), ks = tid>>6 (k-quarter).
#define SREC 516   // padded row stride to dodge bank conflicts on sH

__global__ void lstm_step(float* __restrict__ out, int t) {
    __shared__ __align__(16) float sH[16][SREC];
    __shared__ float sRed[3][64][16];

    const int tid = threadIdx.x;
    const int hg = blockIdx.x & 31, bg = blockIdx.x >> 5;
    const int h0 = hg * 16, b0 = bg * 16;
    const int h_l = tid & 15, bq = (tid >> 4) & 3, ks = tid >> 6;
    const int h = h0 + h_l;

    // stage h_{t-1} for this CTA's 16 batches (from out[b][t-1][:], zeros at t=0)
    if (t == 0) {
        for (int i = tid; i < 16 * 128; i += 256) {
            int r = i >> 7, c4 = i & 127;
            *(float4*)&sH[r][c4 * 4] = make_float4(0.f, 0.f, 0.f, 0.f);
        }
    } else {
        const float* hprev = out + (size_t)(t - 1) * H_;
        for (int i = tid; i < 16 * 128; i += 256) {
            int r = i >> 7, c4 = i & 127;
            *(float4*)&sH[r][c4 * 4] =
                *(const float4*)(hprev + (size_t)(b0 + r) * T_ * H_ + c4 * 4);
        }
    }
    __syncthreads();

    // accumulate 4 gates for 4 b's over this thread's k-quarter
    ull acc[4][2];   // [b][(c,i) | (f,o)]
#pragma unroll
    for (int b = 0; b < 4; b++) { acc[b][0] = 0ull; acc[b][1] = 0ull; }

    const int kbeg = ks * 128;
    const ulonglong2* __restrict__ Ucol = g_U4 + h;
#pragma unroll 4
    for (int k = kbeg; k < kbeg + 128; k++) {
        ulonglong2 u = Ucol[(size_t)k * H_];   // (uc,ui | uf,uo) for (k,h)
#pragma unroll
        for (int b = 0; b < 4; b++) {
            ull hp = pack2(sH[bq * 4 + b][k]);
            ffma2(acc[b][0], hp, u.x);
            ffma2(acc[b][1], hp, u.y);
        }
    }

    const int g64 = tid & 63;
    if (ks > 0) {
#pragma unroll
        for (int b = 0; b < 4; b++) {
            float2 v0 = up2(acc[b][0]), v1 = up2(acc[b][1]);
            sRed[ks - 1][g64][b * 4 + 0] = v0.x;
            sRed[ks - 1][g64][b * 4 + 1] = v0.y;
            sRed[ks - 1][g64][b * 4 + 2] = v1.x;
            sRed[ks - 1][g64][b * 4 + 3] = v1.y;
        }
    }
    __syncthreads();

    if (ks == 0) {
        const float* Pt = g_P + (size_t)t * B_ * 2048;
#pragma unroll
        for (int b = 0; b < 4; b++) {
            const int bglob = b0 + bq * 4 + b;
            float2 v0 = up2(acc[b][0]), v1 = up2(acc[b][1]);
            float pre[4] = {v0.x, v0.y, v1.x, v1.y};   // c, i, f, o
#pragma unroll
            for (int s = 0; s < 3; s++)
#pragma unroll
                for (int g = 0; g < 4; g++) pre[g] += sRed[s][g64][b * 4 + g];

            const float* Pb = Pt + (size_t)bglob * 2048 + h;
            pre[0] += __ldg(Pb);
            pre[1] += __ldg(Pb + 512);
            pre[2] += __ldg(Pb + 1024);
            pre[3] += __ldg(Pb + 1536);

            float a  = tanhf(pre[0]);
            float ig = 1.f / (1.f + expf(-pre[1]));
            float fg = 1.f / (1.f + expf(-pre[2]));
            float og = 1.f / (1.f + expf(-pre[3]));
            float cprev = (t > 0) ? g_c[(size_t)bglob * H_ + h] : 0.f;
            float cn = ig * a + fg * cprev;
            g_c[(size_t)bglob * H_ + h] = cn;
            out[((size_t)bglob * T_ + t) * H_ + h] = og * tanhf(cn);
        }
    }
}

// ---------------- launch ----------------
extern "C" void kernel_launch(void* const* d_in, const int* in_sizes, int n_in,
                              void* d_out, int out_size) {
    const float* x  = (const float*)d_in[0];
    const float* Wc = (const float*)d_in[1];
    const float* Wi = (const float*)d_in[2];
    const float* Wf = (const float*)d_in[3];
    const float* Wo = (const float*)d_in[4];
    const float* Uc = (const float*)d_in[5];
    const float* Ui = (const float*)d_in[6];
    const float* Uf = (const float*)d_in[7];
    const float* Uo = (const float*)d_in[8];
    const float* bc = (const float*)d_in[9];
    const float* bi = (const float*)d_in[10];
    const float* bf = (const float*)d_in[11];
    const float* bo = (const float*)d_in[12];
    float* out = (float*)d_out;

    build_u4<<<(D_ * H_) / 256, 256>>>(Uc, Ui, Uf, Uo);

    dim3 ggrid(2048 / BN, (B_ * T_) / BM);   // (16, 256)
    gemm_pre<<<ggrid, 256>>>(x, Wc, Wi, Wf, Wo, bc, bi, bf, bo);

    for (int t = 0; t < T_; t++) {
        lstm_step<<<128, 256>>>(out, t);
    }
}

// round 8
// speedup vs baseline: 1.7702x; 1.7702x over previous
#include <cuda_runtime.h>
#include <cuda_bf16.h>
#include <cstdint>
#include <cstddef>

// LSTM: B=64, T=512, D=512, H=512, fp32.
// Phase 0: interleave U gates -> g_U4[k*512+h] = (Uc,Ui,Uf,Uo)[k][h]
// Phase 1: P[t][b][g*512+h] = x @ W_g + b_g  (SGEMM, f32x2 FFMA)
// Phase 2: ONE persistent kernel, 128 CTAs, U register-resident, c in regs,
//          h ping-ponged through global k-major buffer, global barrier per step.

typedef unsigned long long ull;

#define B_ 64
#define T_ 512
#define D_ 512
#define H_ 512

// ---------------- device scratch (static: no allocation APIs) ----------------
__device__ float      g_P[(size_t)T_ * B_ * 2048];   // 256 MB preactivations
__device__ ulonglong2 g_U4[(size_t)D_ * H_];         // 4 MB gate-interleaved U
__device__ float      g_h2[2][(size_t)H_ * B_];      // ping-pong h, layout [h][b]
__device__ unsigned   g_count;                        // cumulative barrier counter

// ---------------- f32x2 helpers ----------------
__device__ __forceinline__ void ffma2(ull& d, ull a, ull b) {
    asm("fma.rn.f32x2 %0, %1, %2, %0;" : "+l"(d) : "l"(a), "l"(b));
}
__device__ __forceinline__ ull pack2(float v) {
    ull r; asm("mov.b64 %0, {%1, %1};" : "=l"(r) : "f"(v)); return r;
}
__device__ __forceinline__ float2 up2(ull v) {
    float2 r; asm("mov.b64 {%0, %1}, %2;" : "=f"(r.x), "=f"(r.y) : "l"(v)); return r;
}
__device__ __forceinline__ unsigned ldv(const unsigned* p) {
    unsigned v; asm volatile("ld.volatile.global.u32 %0, [%1];" : "=r"(v) : "l"(p)); return v;
}

// ---------------- phase 0: build interleaved U + reset state ----------------
__global__ void build_u4(const float* __restrict__ Uc, const float* __restrict__ Ui,
                         const float* __restrict__ Uf, const float* __restrict__ Uo) {
    int i = blockIdx.x * 256 + threadIdx.x;   // i = k*512 + h
    float4 v = make_float4(Uc[i], Ui[i], Uf[i], Uo[i]);
    ((float4*)g_U4)[i] = v;
}

__global__ void zero_init() {
    int i = blockIdx.x * 256 + threadIdx.x;   // 128*256 = 32768 = H_*B_
    g_h2[0][i] = 0.f;
    if (i == 0) g_count = 0u;
}

// ---------------- phase 1: SGEMM for preactivations ----------------
#define BM 128
#define BN 128
#define BK 8

__global__ void gemm_pre(const float* __restrict__ A,
                         const float* __restrict__ Wc, const float* __restrict__ Wi,
                         const float* __restrict__ Wf, const float* __restrict__ Wo,
                         const float* __restrict__ bc, const float* __restrict__ bi,
                         const float* __restrict__ bf, const float* __restrict__ bo) {
    __shared__ __align__(16) float As[BK][BM];
    __shared__ __align__(16) float Bs[BK][BN];

    const int tid   = threadIdx.x;
    const int ntile = blockIdx.x;              // 0..15
    const int m0    = blockIdx.y * BM;
    const int gate  = ntile >> 2;
    const int hbase = (ntile & 3) * BN;
    const float* W    = (gate == 0) ? Wc : (gate == 1) ? Wi : (gate == 2) ? Wf : Wo;
    const float* bias = (gate == 0) ? bc : (gate == 1) ? bi : (gate == 2) ? bf : bo;

    const int a_row = tid >> 1, a_col = (tid & 1) * 4;
    const int b_row = tid >> 5, b_col = (tid & 31) * 4;
    const int tx = tid & 15, ty = tid >> 4;

    ull acc[4][8];
#pragma unroll
    for (int i = 0; i < 4; i++)
#pragma unroll
        for (int j = 0; j < 8; j++) acc[i][j] = 0ull;

    const float* Abase = A + (size_t)(m0 + a_row) * D_ + a_col;
    const float* Wbase = W + (size_t)b_row * H_ + hbase + b_col;

    for (int k0 = 0; k0 < D_; k0 += BK) {
        float4 av = *(const float4*)(Abase + k0);
        As[a_col + 0][a_row] = av.x;
        As[a_col + 1][a_row] = av.y;
        As[a_col + 2][a_row] = av.z;
        As[a_col + 3][a_row] = av.w;
        *(float4*)&Bs[b_row][b_col] = *(const float4*)(Wbase + (size_t)k0 * H_);
        __syncthreads();

#pragma unroll
        for (int kk = 0; kk < BK; kk++) {
            const ull* a64 = (const ull*)&As[kk][0];
            ull aP[4];
            aP[0] = a64[ty * 2];
            aP[1] = a64[ty * 2 + 1];
            aP[2] = a64[ty * 2 + 32];
            aP[3] = a64[ty * 2 + 33];
            float4 bv0 = *(const float4*)&Bs[kk][tx * 4];
            float4 bv1 = *(const float4*)&Bs[kk][tx * 4 + 64];
            ull bp[8];
            bp[0] = pack2(bv0.x); bp[1] = pack2(bv0.y);
            bp[2] = pack2(bv0.z); bp[3] = pack2(bv0.w);
            bp[4] = pack2(bv1.x); bp[5] = pack2(bv1.y);
            bp[6] = pack2(bv1.z); bp[7] = pack2(bv1.w);
#pragma unroll
            for (int ip = 0; ip < 4; ip++)
#pragma unroll
                for (int j = 0; j < 8; j++) ffma2(acc[ip][j], aP[ip], bp[j]);
        }
        __syncthreads();
    }

    float bias0[4], bias1[4];
#pragma unroll
    for (int j = 0; j < 4; j++) {
        bias0[j] = __ldg(&bias[hbase + tx * 4 + j]);
        bias1[j] = __ldg(&bias[hbase + 64 + tx * 4 + j]);
    }
#pragma unroll
    for (int ip = 0; ip < 4; ip++) {
        const int m_l = (ip < 2) ? (ty * 4 + ip * 2) : (64 + ty * 4 + (ip - 2) * 2);
        float2 c0 = up2(acc[ip][0]), c1 = up2(acc[ip][1]);
        float2 c2 = up2(acc[ip][2]), c3 = up2(acc[ip][3]);
        float2 c4 = up2(acc[ip][4]), c5 = up2(acc[ip][5]);
        float2 c6 = up2(acc[ip][6]), c7 = up2(acc[ip][7]);
#pragma unroll
        for (int lane = 0; lane < 2; lane++) {
            const int row = m0 + m_l + lane;        // row = b*512 + t
            const int b = row >> 9, t = row & 511;
            float* dst = g_P + ((size_t)(t * B_ + b)) * 2048 + (size_t)gate * 512 + hbase;
            float4 v0, v1;
            if (lane == 0) {
                v0 = make_float4(c0.x + bias0[0], c1.x + bias0[1], c2.x + bias0[2], c3.x + bias0[3]);
                v1 = make_float4(c4.x + bias1[0], c5.x + bias1[1], c6.x + bias1[2], c7.x + bias1[3]);
            } else {
                v0 = make_float4(c0.y + bias0[0], c1.y + bias0[1], c2.y + bias0[2], c3.y + bias0[3]);
                v1 = make_float4(c4.y + bias1[0], c5.y + bias1[1], c6.y + bias1[2], c7.y + bias1[3]);
            }
            *(float4*)(dst + tx * 4)      = v0;
            *(float4*)(dst + 64 + tx * 4) = v1;
        }
    }
}

// ---------------- phase 2: persistent recurrence ----------------
// 128 CTAs = 4 b-groups x 32 h-groups. CTA tile: 16 b x 16 h.
// Thread: h_l = tid&15 (its h), ks = tid>>4 (its 32-k quarter... 16 groups of 32 k).
// U slice (32 k x 4 gates) lives in 64 ull registers for the whole sequence.
// Epilogue identity: (b = tid>>4, h = tid&15); c state in a register.

#define SH_STRIDE 36                       // floats per sHd row (32 data + 4 pad)
#define SHD_FLOATS (D_ * SH_STRIDE)        // 18432 floats = 73728 B
#define SRED_ULLS  (16 * 16 * 34)          // 8704 ull = 69632 B
#define SMEM_REC   (SHD_FLOATS * 4 + SRED_ULLS * 8)

__global__ void __launch_bounds__(256, 1) lstm_rec(float* __restrict__ out) {
    extern __shared__ __align__(16) char smem[];
    float* sHd = (float*)smem;                          // [512][36] duplicated h pairs
    ull*   sRed = (ull*)(smem + SHD_FLOATS * 4);        // [16 ks][16 h][34]

    const int tid = threadIdx.x;
    const int hg = blockIdx.x & 31, bg = blockIdx.x >> 5;
    const int h0 = hg * 16, b0 = bg * 16;
    const int h_l = tid & 15, ks = tid >> 4;            // ks doubles as epilogue b
    const int kbase = ks * 32;

    // prologue: U slice into registers (lives across all 512 steps)
    ull uA[32], uB[32];
#pragma unroll
    for (int i = 0; i < 32; i++) {
        ulonglong2 v = g_U4[(size_t)(kbase + i) * H_ + h0 + h_l];
        uA[i] = v.x;                                    // (Uc, Ui)
        uB[i] = v.y;                                    // (Uf, Uo)
    }

    float c_reg = 0.f;
    const float* Pbase = g_P + (size_t)(b0 + ks) * 2048 + h0 + h_l;

    for (int t = 0; t < T_; t++) {
        // prefetch this step's input preactivations (consumed ~4000 cyc later)
        const float* Pt = Pbase + (size_t)t * B_ * 2048;
        float p0 = __ldg(Pt);
        float p1 = __ldg(Pt + 512);
        float p2 = __ldg(Pt + 1024);
        float p3 = __ldg(Pt + 1536);

        // stage h_{t-1}: global [h][b] -> smem duplicated pairs {h,h}
        {
            const float* hb = g_h2[t & 1];
#pragma unroll
            for (int task = tid; task < 2048; task += 256) {
                int k = task >> 2, q = task & 3;
                float4 v = *(const float4*)(hb + (size_t)k * B_ + b0 + q * 4);
                float4 w0 = make_float4(v.x, v.x, v.y, v.y);
                float4 w1 = make_float4(v.z, v.z, v.w, v.w);
                *(float4*)&sHd[k * SH_STRIDE + q * 8]     = w0;
                *(float4*)&sHd[k * SH_STRIDE + q * 8 + 4] = w1;
            }
        }
        __syncthreads();

        // partial gate sums over this thread's 32-k slice, all 16 b's
        ull acc[16][2];
#pragma unroll
        for (int b = 0; b < 16; b++) { acc[b][0] = 0ull; acc[b][1] = 0ull; }

#pragma unroll
        for (int i = 0; i < 32; i++) {
            const ulonglong2* row = (const ulonglong2*)&sHd[(kbase + i) * SH_STRIDE];
            ull ua = uA[i], ub = uB[i];
#pragma unroll
            for (int bq = 0; bq < 8; bq++) {
                ulonglong2 hp = row[bq];                // {h_{2bq} dup, h_{2bq+1} dup}
                ffma2(acc[2 * bq][0],     hp.x, ua);
                ffma2(acc[2 * bq][1],     hp.x, ub);
                ffma2(acc[2 * bq + 1][0], hp.y, ua);
                ffma2(acc[2 * bq + 1][1], hp.y, ub);
            }
        }

        // dump partials to smem for cross-ks reduction
        {
            ull* rb = sRed + (ks * 16 + h_l) * 34;
#pragma unroll
            for (int b = 0; b < 16; b++) {
                rb[2 * b]     = acc[b][0];
                rb[2 * b + 1] = acc[b][1];
            }
        }
        __syncthreads();

        // epilogue: thread owns (b = ks, h = h_l)
        {
            float pc = p0, pi = p1, pf = p2, po = p3;
#pragma unroll
            for (int kk = 0; kk < 16; kk++) {
                const ull* r = sRed + (kk * 16 + h_l) * 34 + 2 * ks;
                float2 v0 = up2(r[0]);
                float2 v1 = up2(r[1]);
                pc += v0.x; pi += v0.y; pf += v1.x; po += v1.y;
            }
            float a  = tanhf(pc);
            float ig = 1.f / (1.f + __expf(-pi));
            float fg = 1.f / (1.f + __expf(-pf));
            float og = 1.f / (1.f + __expf(-po));
            c_reg = ig * a + fg * c_reg;
            float hn = og * tanhf(c_reg);

            out[((size_t)(b0 + ks) * T_ + t) * H_ + h0 + h_l] = hn;
            g_h2[(t + 1) & 1][(size_t)(h0 + h_l) * B_ + b0 + ks] = hn;
        }

        // inter-CTA barrier (skip after last step)
        if (t < T_ - 1) {
            __threadfence();
            __syncthreads();
            if (tid == 0) {
                atomicAdd(&g_count, 1u);
                unsigned target = 128u * (unsigned)(t + 1);
                while (ldv(&g_count) < target) {}
                __threadfence();
            }
            __syncthreads();
        }
    }
}

// ---------------- launch ----------------
extern "C" void kernel_launch(void* const* d_in, const int* in_sizes, int n_in,
                              void* d_out, int out_size) {
    const float* x  = (const float*)d_in[0];
    const float* Wc = (const float*)d_in[1];
    const float* Wi = (const float*)d_in[2];
    const float* Wf = (const float*)d_in[3];
    const float* Wo = (const float*)d_in[4];
    const float* Uc = (const float*)d_in[5];
    const float* Ui = (const float*)d_in[6];
    const float* Uf = (const float*)d_in[7];
    const float* Uo = (const float*)d_in[8];
    const float* bc = (const float*)d_in[9];
    const float* bi = (const float*)d_in[10];
    const float* bf = (const float*)d_in[11];
    const float* bo = (const float*)d_in[12];
    float* out = (float*)d_out;

    static bool attr_set = false;
    if (!attr_set) {
        cudaFuncSetAttribute(lstm_rec, cudaFuncAttributeMaxDynamicSharedMemorySize, SMEM_REC);
        attr_set = true;
    }

    zero_init<<<128, 256>>>();
    build_u4<<<(D_ * H_) / 256, 256>>>(Uc, Ui, Uf, Uo);

    dim3 ggrid(2048 / BN, (B_ * T_) / BM);   // (16, 256)
    gemm_pre<<<ggrid, 256>>>(x, Wc, Wi, Wf, Wo, bc, bi, bf, bo);

    lstm_rec<<<128, 256, SMEM_REC>>>(out);
}

// round 9
// speedup vs baseline: 1.7906x; 1.0115x over previous
#include <cuda_runtime.h>
#include <cuda_bf16.h>
#include <cstdint>
#include <cstddef>

// LSTM: B=64, T=512, D=512, H=512, fp32.
// Phase 0: interleave U gates -> g_U4[k*512+h] = (Uc,Ui,Uf,Uo)[k][h]
// Phase 1: P[t][b][g*512+h] = x @ W_g + b_g  (SGEMM, f32x2 FFMA)
// Phase 2: ONE persistent kernel, 128 CTAs, U register-resident (no spills:
//          b accumulated in 2 halves), per-batch-group barriers.

typedef unsigned long long ull;

#define B_ 64
#define T_ 512
#define D_ 512
#define H_ 512

// ---------------- device scratch (static: no allocation APIs) ----------------
__device__ float      g_P[(size_t)T_ * B_ * 2048];   // 256 MB preactivations
__device__ ulonglong2 g_U4[(size_t)D_ * H_];         // 4 MB gate-interleaved U
__device__ float      g_h2[2][(size_t)H_ * B_];      // ping-pong h, layout [h][b]
__device__ unsigned   g_cnt[4 * 32];                  // per-bg barrier counters (128B apart)

// ---------------- f32x2 helpers ----------------
__device__ __forceinline__ void ffma2(ull& d, ull a, ull b) {
    asm("fma.rn.f32x2 %0, %1, %2, %0;" : "+l"(d) : "l"(a), "l"(b));
}
__device__ __forceinline__ ull pack2(float v) {
    ull r; asm("mov.b64 %0, {%1, %1};" : "=l"(r) : "f"(v)); return r;
}
__device__ __forceinline__ float2 up2(ull v) {
    float2 r; asm("mov.b64 {%0, %1}, %2;" : "=f"(r.x), "=f"(r.y) : "l"(v)); return r;
}
__device__ __forceinline__ unsigned ldv(const unsigned* p) {
    unsigned v; asm volatile("ld.volatile.global.u32 %0, [%1];" : "=r"(v) : "l"(p)); return v;
}

// ---------------- phase 0: build interleaved U + reset state ----------------
__global__ void build_u4(const float* __restrict__ Uc, const float* __restrict__ Ui,
                         const float* __restrict__ Uf, const float* __restrict__ Uo) {
    int i = blockIdx.x * 256 + threadIdx.x;   // i = k*512 + h
    float4 v = make_float4(Uc[i], Ui[i], Uf[i], Uo[i]);
    ((float4*)g_U4)[i] = v;
}

__global__ void zero_init() {
    int i = blockIdx.x * 256 + threadIdx.x;   // 128*256 = 32768 = H_*B_
    g_h2[0][i] = 0.f;
    if (i < 4 * 32) g_cnt[i] = 0u;
}

// ---------------- phase 1: SGEMM for preactivations ----------------
#define BM 128
#define BN 128
#define BK 8

__global__ void gemm_pre(const float* __restrict__ A,
                         const float* __restrict__ Wc, const float* __restrict__ Wi,
                         const float* __restrict__ Wf, const float* __restrict__ Wo,
                         const float* __restrict__ bc, const float* __restrict__ bi,
                         const float* __restrict__ bf, const float* __restrict__ bo) {
    __shared__ __align__(16) float As[BK][BM];
    __shared__ __align__(16) float Bs[BK][BN];

    const int tid   = threadIdx.x;
    const int ntile = blockIdx.x;              // 0..15
    const int m0    = blockIdx.y * BM;
    const int gate  = ntile >> 2;
    const int hbase = (ntile & 3) * BN;
    const float* W    = (gate == 0) ? Wc : (gate == 1) ? Wi : (gate == 2) ? Wf : Wo;
    const float* bias = (gate == 0) ? bc : (gate == 1) ? bi : (gate == 2) ? bf : bo;

    const int a_row = tid >> 1, a_col = (tid & 1) * 4;
    const int b_row = tid >> 5, b_col = (tid & 31) * 4;
    const int tx = tid & 15, ty = tid >> 4;

    ull acc[4][8];
#pragma unroll
    for (int i = 0; i < 4; i++)
#pragma unroll
        for (int j = 0; j < 8; j++) acc[i][j] = 0ull;

    const float* Abase = A + (size_t)(m0 + a_row) * D_ + a_col;
    const float* Wbase = W + (size_t)b_row * H_ + hbase + b_col;

    for (int k0 = 0; k0 < D_; k0 += BK) {
        float4 av = *(const float4*)(Abase + k0);
        As[a_col + 0][a_row] = av.x;
        As[a_col + 1][a_row] = av.y;
        As[a_col + 2][a_row] = av.z;
        As[a_col + 3][a_row] = av.w;
        *(float4*)&Bs[b_row][b_col] = *(const float4*)(Wbase + (size_t)k0 * H_);
        __syncthreads();

#pragma unroll
        for (int kk = 0; kk < BK; kk++) {
            const ull* a64 = (const ull*)&As[kk][0];
            ull aP[4];
            aP[0] = a64[ty * 2];
            aP[1] = a64[ty * 2 + 1];
            aP[2] = a64[ty * 2 + 32];
            aP[3] = a64[ty * 2 + 33];
            float4 bv0 = *(const float4*)&Bs[kk][tx * 4];
            float4 bv1 = *(const float4*)&Bs[kk][tx * 4 + 64];
            ull bp[8];
            bp[0] = pack2(bv0.x); bp[1] = pack2(bv0.y);
            bp[2] = pack2(bv0.z); bp[3] = pack2(bv0.w);
            bp[4] = pack2(bv1.x); bp[5] = pack2(bv1.y);
            bp[6] = pack2(bv1.z); bp[7] = pack2(bv1.w);
#pragma unroll
            for (int ip = 0; ip < 4; ip++)
#pragma unroll
                for (int j = 0; j < 8; j++) ffma2(acc[ip][j], aP[ip], bp[j]);
        }
        __syncthreads();
    }

    float bias0[4], bias1[4];
#pragma unroll
    for (int j = 0; j < 4; j++) {
        bias0[j] = __ldg(&bias[hbase + tx * 4 + j]);
        bias1[j] = __ldg(&bias[hbase + 64 + tx * 4 + j]);
    }
#pragma unroll
    for (int ip = 0; ip < 4; ip++) {
        const int m_l = (ip < 2) ? (ty * 4 + ip * 2) : (64 + ty * 4 + (ip - 2) * 2);
        float2 c0 = up2(acc[ip][0]), c1 = up2(acc[ip][1]);
        float2 c2 = up2(acc[ip][2]), c3 = up2(acc[ip][3]);
        float2 c4 = up2(acc[ip][4]), c5 = up2(acc[ip][5]);
        float2 c6 = up2(acc[ip][6]), c7 = up2(acc[ip][7]);
#pragma unroll
        for (int lane = 0; lane < 2; lane++) {
            const int row = m0 + m_l + lane;        // row = b*512 + t
            const int b = row >> 9, t = row & 511;
            float* dst = g_P + ((size_t)(t * B_ + b)) * 2048 + (size_t)gate * 512 + hbase;
            float4 v0, v1;
            if (lane == 0) {
                v0 = make_float4(c0.x + bias0[0], c1.x + bias0[1], c2.x + bias0[2], c3.x + bias0[3]);
                v1 = make_float4(c4.x + bias1[0], c5.x + bias1[1], c6.x + bias1[2], c7.x + bias1[3]);
            } else {
                v0 = make_float4(c0.y + bias0[0], c1.y + bias0[1], c2.y + bias0[2], c3.y + bias0[3]);
                v1 = make_float4(c4.y + bias1[0], c5.y + bias1[1], c6.y + bias1[2], c7.y + bias1[3]);
            }
            *(float4*)(dst + tx * 4)      = v0;
            *(float4*)(dst + 64 + tx * 4) = v1;
        }
    }
}

// ---------------- phase 2: persistent recurrence ----------------
// 128 CTAs = 4 b-groups x 32 h-groups. CTA tile: 16 b x 16 h.
// Thread: h_l = tid&15, ks = tid>>4 (32-k slice). U slice = 64 ull registers.
// Batches accumulated in TWO halves of 8 to keep regs < 255 (no spills).
// Barrier is per-batch-group (32 CTAs, private counter).

#define SH_STRIDE 36                       // floats per sHd row (32 data + 4 pad)
#define SHD_FLOATS (D_ * SH_STRIDE)        // 18432 floats = 73728 B
#define SRED_ULLS  (16 * 16 * 34)          // [ks][h][16b*2 + pad]
#define SMEM_REC   (SHD_FLOATS * 4 + SRED_ULLS * 8)

__global__ void __launch_bounds__(256, 1) lstm_rec(float* __restrict__ out) {
    extern __shared__ __align__(16) char smem[];
    float* sHd = (float*)smem;                          // [512][36] duplicated h pairs
    ull*   sRed = (ull*)(smem + SHD_FLOATS * 4);        // [16 ks][16 h][34]

    const int tid = threadIdx.x;
    const int hg = blockIdx.x & 31, bg = blockIdx.x >> 5;
    const int h0 = hg * 16, b0 = bg * 16;
    const int h_l = tid & 15, ks = tid >> 4;            // ks doubles as epilogue b
    const int kbase = ks * 32;
    unsigned* bar = &g_cnt[bg * 32];

    // prologue: U slice into registers (lives across all 512 steps)
    ull uA[32], uB[32];
#pragma unroll
    for (int i = 0; i < 32; i++) {
        ulonglong2 v = g_U4[(size_t)(kbase + i) * H_ + h0 + h_l];
        uA[i] = v.x;                                    // (Uc, Ui)
        uB[i] = v.y;                                    // (Uf, Uo)
    }

    float c_reg = 0.f;
    const float* Pbase = g_P + (size_t)(b0 + ks) * 2048 + h0 + h_l;

    for (int t = 0; t < T_; t++) {
        // stage h_{t-1}: global [h][b] -> smem duplicated pairs {h,h}
        // (issue all 8 LDG.128 first for MLP, then store)
        {
            const float* hb = g_h2[t & 1];
            float4 v[8];
#pragma unroll
            for (int j = 0; j < 8; j++) {
                int task = tid + j * 256;
                int k = task >> 2, q = task & 3;
                v[j] = *(const float4*)(hb + (size_t)k * B_ + b0 + q * 4);
            }
#pragma unroll
            for (int j = 0; j < 8; j++) {
                int task = tid + j * 256;
                int k = task >> 2, q = task & 3;
                *(float4*)&sHd[k * SH_STRIDE + q * 8] =
                    make_float4(v[j].x, v[j].x, v[j].y, v[j].y);
                *(float4*)&sHd[k * SH_STRIDE + q * 8 + 4] =
                    make_float4(v[j].z, v[j].z, v[j].w, v[j].w);
            }
        }

        // prefetch this step's input preactivations
        const float* Pt = Pbase + (size_t)t * B_ * 2048;
        float p0 = __ldg(Pt);
        float p1 = __ldg(Pt + 512);
        float p2 = __ldg(Pt + 1024);
        float p3 = __ldg(Pt + 1536);

        __syncthreads();

        // partial gate sums over this thread's 32-k slice; batches in 2 halves
        ull* rb = sRed + (ks * 16 + h_l) * 34;
#pragma unroll
        for (int half = 0; half < 2; half++) {
            ull acc[8][2];
#pragma unroll
            for (int b = 0; b < 8; b++) { acc[b][0] = 0ull; acc[b][1] = 0ull; }

#pragma unroll
            for (int i = 0; i < 32; i++) {
                const ulonglong2* row =
                    (const ulonglong2*)&sHd[(kbase + i) * SH_STRIDE] + half * 4;
                ull ua = uA[i], ub = uB[i];
#pragma unroll
                for (int bq = 0; bq < 4; bq++) {
                    ulonglong2 hp = row[bq];            // {h dup, h' dup}
                    ffma2(acc[2 * bq][0],     hp.x, ua);
                    ffma2(acc[2 * bq][1],     hp.x, ub);
                    ffma2(acc[2 * bq + 1][0], hp.y, ua);
                    ffma2(acc[2 * bq + 1][1], hp.y, ub);
                }
            }
#pragma unroll
            for (int b = 0; b < 8; b++) {
                rb[(half * 8 + b) * 2]     = acc[b][0];
                rb[(half * 8 + b) * 2 + 1] = acc[b][1];
            }
        }
        __syncthreads();

        // epilogue: thread owns (b = ks, h = h_l)
        {
            float pc = p0, pi = p1, pf = p2, po = p3;
#pragma unroll
            for (int kk = 0; kk < 16; kk++) {
                const ull* r = sRed + (kk * 16 + h_l) * 34 + 2 * ks;
                float2 v0 = up2(r[0]);
                float2 v1 = up2(r[1]);
                pc += v0.x; pi += v0.y; pf += v1.x; po += v1.y;
            }
            float a  = tanhf(pc);
            float ig = 1.f / (1.f + __expf(-pi));
            float fg = 1.f / (1.f + __expf(-pf));
            float og = 1.f / (1.f + __expf(-po));
            c_reg = ig * a + fg * c_reg;
            float hn = og * tanhf(c_reg);

            out[((size_t)(b0 + ks) * T_ + t) * H_ + h0 + h_l] = hn;
            g_h2[(t + 1) & 1][(size_t)(h0 + h_l) * B_ + b0 + ks] = hn;
        }

        // inter-CTA barrier, scoped to this batch-group (32 CTAs)
        if (t < T_ - 1) {
            __threadfence();
            __syncthreads();
            if (tid == 0) {
                atomicAdd(bar, 1u);
                unsigned target = 32u * (unsigned)(t + 1);
                while (ldv(bar) < target) {}
                __threadfence();
            }
            __syncthreads();
        }
    }
}

// ---------------- launch ----------------
extern "C" void kernel_launch(void* const* d_in, const int* in_sizes, int n_in,
                              void* d_out, int out_size) {
    const float* x  = (const float*)d_in[0];
    const float* Wc = (const float*)d_in[1];
    const float* Wi = (const float*)d_in[2];
    const float* Wf = (const float*)d_in[3];
    const float* Wo = (const float*)d_in[4];
    const float* Uc = (const float*)d_in[5];
    const float* Ui = (const float*)d_in[6];
    const float* Uf = (const float*)d_in[7];
    const float* Uo = (const float*)d_in[8];
    const float* bc = (const float*)d_in[9];
    const float* bi = (const float*)d_in[10];
    const float* bf = (const float*)d_in[11];
    const float* bo = (const float*)d_in[12];
    float* out = (float*)d_out;

    static bool attr_set = false;
    if (!attr_set) {
        cudaFuncSetAttribute(lstm_rec, cudaFuncAttributeMaxDynamicSharedMemorySize, SMEM_REC);
        attr_set = true;
    }

    zero_init<<<128, 256>>>();
    build_u4<<<(D_ * H_) / 256, 256>>>(Uc, Ui, Uf, Uo);

    dim3 ggrid(2048 / BN, (B_ * T_) / BM);   // (16, 256)
    gemm_pre<<<ggrid, 256>>>(x, Wc, Wi, Wf, Wo, bc, bi, bf, bo);

    lstm_rec<<<128, 256, SMEM_REC>>>(out);
}